// round 2
// baseline (speedup 1.0000x reference)
#include <cuda_runtime.h>
#include <cstdint>

// Problem constants
#define NB   32      // batch
#define CIN  64
#define COUT 64
#define TT   6
#define VV   512
#define TV   (TT*VV)            // 3072
#define XC_ELEMS (NB*COUT*TV)   // 6,291,456
#define A4_ELEMS (NB*VV*VV)     // 8,388,608
#define NEG_FILL  (-1000.0f)
#define SLOPE     (0.2f)

// Scratch (device globals; no allocation allowed)
__device__ float g_xc[XC_ELEMS];     // (n, c, t, v)
__device__ float g_si[NB*VV];
__device__ float g_sj[NB*VV];

// ---------------------------------------------------------------------------
// Kernel 1: xc[n,o,t,v] = sum_i W[o,i]*x[n,i,t,v] + b[o]
// grid (24, 32) blocks of 256 threads, 128 (t,v)-columns per block
// ---------------------------------------------------------------------------
__global__ __launch_bounds__(256) void k_conv(const float* __restrict__ x,
                                              const float* __restrict__ W,
                                              const float* __restrict__ b) {
    __shared__ float sW[COUT*CIN];        // 16 KB
    __shared__ float sX[CIN][128];        // 32 KB
    const int n  = blockIdx.y;
    const int p0 = blockIdx.x * 128;
    const int tid = threadIdx.x;

    for (int idx = tid; idx < COUT*CIN; idx += 256) sW[idx] = W[idx];
    const float* xb = x + (size_t)n * CIN * TV;
    for (int idx = tid; idx < CIN*128; idx += 256) {
        int i = idx >> 7, c = idx & 127;
        sX[i][c] = xb[i*TV + p0 + c];
    }
    __syncthreads();

    const int tx = tid & 31;   // 4 columns each
    const int ty = tid >> 5;   // 8 output channels each
    float acc[8][4];
    #pragma unroll
    for (int a = 0; a < 8; a++)
        #pragma unroll
        for (int q = 0; q < 4; q++) acc[a][q] = 0.f;

    #pragma unroll 8
    for (int i = 0; i < CIN; i++) {
        float4 xv = *(const float4*)&sX[i][tx*4];
        #pragma unroll
        for (int a = 0; a < 8; a++) {
            float w = sW[(ty*8 + a)*CIN + i];
            acc[a][0] += w * xv.x;
            acc[a][1] += w * xv.y;
            acc[a][2] += w * xv.z;
            acc[a][3] += w * xv.w;
        }
    }

    float* xcb = g_xc + (size_t)n * COUT * TV;
    #pragma unroll
    for (int a = 0; a < 8; a++) {
        int o = ty*8 + a;
        float bias = b[o];
        float4 r = make_float4(acc[a][0]+bias, acc[a][1]+bias,
                               acc[a][2]+bias, acc[a][3]+bias);
        *(float4*)&xcb[o*TV + p0 + tx*4] = r;
    }
}

// ---------------------------------------------------------------------------
// Kernel 2: x10[n,v,c] = sum_t xc[n,c,t,v]*l2w[t] + l2b
//           s_i[n,v] = x10 . w_src ; s_j[n,v] = x10 . w_dst   (fused)
// ---------------------------------------------------------------------------
__global__ __launch_bounds__(128) void k_x10(const float* __restrict__ l1w,
                                             const float* __restrict__ l2w,
                                             const float* __restrict__ l2b) {
    const int n = blockIdx.y;
    const int v = blockIdx.x * 128 + threadIdx.x;

    float w2[TT];
    #pragma unroll
    for (int t = 0; t < TT; t++) w2[t] = l2w[t];
    const float bias = l2b[0];

    const float* xcb = g_xc + (size_t)n * COUT * TV;
    float si = 0.f, sj = 0.f;
    for (int c = 0; c < COUT; c++) {
        float acc = bias;
        #pragma unroll
        for (int t = 0; t < TT; t++)
            acc += xcb[(c*TT + t)*VV + v] * w2[t];
        si += acc * l1w[c];
        sj += acc * l1w[COUT + c];
    }
    g_si[n*VV + v] = si;
    g_sj[n*VV + v] = sj;
}

// ---------------------------------------------------------------------------
// Kernel 3: scores -> leaky_relu -> mask -> softmax(axis j) -> a4
// grid 16384 = (n, i) rows; 256 threads, 2 j each
// ---------------------------------------------------------------------------
__global__ __launch_bounds__(256) void k_softmax(const float* __restrict__ A,
                                                 const float* __restrict__ l1b,
                                                 float* __restrict__ a4) {
    const int row = blockIdx.x;           // n*512 + i
    const int n = row >> 9;
    const int i = row & 511;
    const int tid = threadIdx.x;
    const int lane = tid & 31, warp = tid >> 5;

    __shared__ float red[10];

    const float si = g_si[row];
    const float* sjp = g_sj + n*VV;
    const float* maskp = A + ((size_t)(n*8 + 7))*VV*VV + (size_t)i*VV;
    const float b = l1b[0];

    float v0, v1;
    {
        int j = tid;
        float s = si + sjp[j] + b;
        s = (s >= 0.f) ? s : SLOPE * s;
        if (maskp[j] == 0.f) s = NEG_FILL;
        v0 = s;
        j = tid + 256;
        s = si + sjp[j] + b;
        s = (s >= 0.f) ? s : SLOPE * s;
        if (maskp[j] == 0.f) s = NEG_FILL;
        v1 = s;
    }

    // max reduction
    float m = fmaxf(v0, v1);
    #pragma unroll
    for (int off = 16; off; off >>= 1) m = fmaxf(m, __shfl_xor_sync(~0u, m, off));
    if (lane == 0) red[warp] = m;
    __syncthreads();
    if (tid == 0) {
        float mm = red[0];
        #pragma unroll
        for (int w = 1; w < 8; w++) mm = fmaxf(mm, red[w]);
        red[8] = mm;
    }
    __syncthreads();
    const float vmax = red[8];

    float e0 = __expf(v0 - vmax);
    float e1 = __expf(v1 - vmax);
    float s = e0 + e1;
    #pragma unroll
    for (int off = 16; off; off >>= 1) s += __shfl_xor_sync(~0u, s, off);
    if (lane == 0) red[warp] = s;
    __syncthreads();
    if (tid == 0) {
        float ss = red[0];
        #pragma unroll
        for (int w = 1; w < 8; w++) ss += red[w];
        red[9] = ss;
    }
    __syncthreads();
    const float inv = 1.0f / red[9];

    float* outp = a4 + (size_t)row * VV;
    outp[tid]       = e0 * inv;
    outp[tid + 256] = e1 * inv;
}

// ---------------------------------------------------------------------------
// Kernel 4: out[n] (384x512) = xc[n] (384x512) @ a4[n] (512x512)
// grid (4, 3, 32). 256 thr, 8x8 accum, register-prefetch double buffering
// ---------------------------------------------------------------------------
__global__ __launch_bounds__(256) void k_gemm(const float* __restrict__ a4,
                                              float* __restrict__ out) {
    const int nb = blockIdx.z;
    const float* Ab = g_xc + (size_t)nb * 384 * 512;
    const float* Bb = a4   + (size_t)nb * 512 * 512;
    float*       Cb = out  + (size_t)nb * 384 * 512;
    const int m0 = blockIdx.y * 128;
    const int n0 = blockIdx.x * 128;

    __shared__ float As[16][128];
    __shared__ float Bs[16][132];   // +4 pad: avoid any row-conflict pattern

    const int tid = threadIdx.x;
    const int tx = tid & 15;     // col group (8 cols)
    const int ty = tid >> 4;     // row group (8 rows)

    // per-thread load coordinates (2 float4 loads each for A and B)
    const int ar0 = (tid*2)     >> 2, ac0 = (tid*2)     & 3;
    const int ar1 = (tid*2 + 1) >> 2, ac1 = (tid*2 + 1) & 3;
    const int br0 = (tid*2)     >> 5, bc0 = (tid*2)     & 31;
    const int br1 = (tid*2 + 1) >> 5, bc1 = (tid*2 + 1) & 31;

    float acc[8][8];
    #pragma unroll
    for (int ii = 0; ii < 8; ii++)
        #pragma unroll
        for (int jj = 0; jj < 8; jj++) acc[ii][jj] = 0.f;

    // prefetch first tile into registers
    float4 pa0 = *(const float4*)&Ab[(size_t)(m0 + ar0)*512 + ac0*4];
    float4 pa1 = *(const float4*)&Ab[(size_t)(m0 + ar1)*512 + ac1*4];
    float4 pb0 = *(const float4*)&Bb[(size_t)br0*512 + n0 + bc0*4];
    float4 pb1 = *(const float4*)&Bb[(size_t)br1*512 + n0 + bc1*4];

    for (int k0 = 0; k0 < 512; k0 += 16) {
        // store prefetched tile to smem
        As[ac0*4+0][ar0] = pa0.x; As[ac0*4+1][ar0] = pa0.y;
        As[ac0*4+2][ar0] = pa0.z; As[ac0*4+3][ar0] = pa0.w;
        As[ac1*4+0][ar1] = pa1.x; As[ac1*4+1][ar1] = pa1.y;
        As[ac1*4+2][ar1] = pa1.z; As[ac1*4+3][ar1] = pa1.w;
        *(float4*)&Bs[br0][bc0*4] = pb0;
        *(float4*)&Bs[br1][bc1*4] = pb1;
        __syncthreads();

        // prefetch next tile (overlaps with compute below)
        if (k0 + 16 < 512) {
            int kn = k0 + 16;
            pa0 = *(const float4*)&Ab[(size_t)(m0 + ar0)*512 + kn + ac0*4];
            pa1 = *(const float4*)&Ab[(size_t)(m0 + ar1)*512 + kn + ac1*4];
            pb0 = *(const float4*)&Bb[(size_t)(kn + br0)*512 + n0 + bc0*4];
            pb1 = *(const float4*)&Bb[(size_t)(kn + br1)*512 + n0 + bc1*4];
        }

        #pragma unroll
        for (int k = 0; k < 16; k++) {
            float a[8], bvals[8];
            *(float4*)(a)       = *(const float4*)&As[k][ty*8];
            *(float4*)(a + 4)   = *(const float4*)&As[k][ty*8 + 4];
            *(float4*)(bvals)   = *(const float4*)&Bs[k][tx*8];
            *(float4*)(bvals+4) = *(const float4*)&Bs[k][tx*8 + 4];
            #pragma unroll
            for (int ii = 0; ii < 8; ii++)
                #pragma unroll
                for (int jj = 0; jj < 8; jj++)
                    acc[ii][jj] += a[ii] * bvals[jj];
        }
        __syncthreads();
    }

    #pragma unroll
    for (int ii = 0; ii < 8; ii++) {
        int r = m0 + ty*8 + ii;
        float4 r0 = make_float4(acc[ii][0], acc[ii][1], acc[ii][2], acc[ii][3]);
        float4 r1 = make_float4(acc[ii][4], acc[ii][5], acc[ii][6], acc[ii][7]);
        *(float4*)&Cb[(size_t)r*512 + n0 + tx*8]     = r0;
        *(float4*)&Cb[(size_t)r*512 + n0 + tx*8 + 4] = r1;
    }
}

// ---------------------------------------------------------------------------
extern "C" void kernel_launch(void* const* d_in, const int* in_sizes, int n_in,
                              void* d_out, int out_size) {
    const float* x      = (const float*)d_in[0];
    const float* A      = (const float*)d_in[1];
    const float* conv_w = (const float*)d_in[2];
    const float* conv_b = (const float*)d_in[3];
    const float* l1_w   = (const float*)d_in[4];
    const float* l1_b   = (const float*)d_in[5];
    const float* l2_w   = (const float*)d_in[6];
    const float* l2_b   = (const float*)d_in[7];

    float* out = (float*)d_out;              // (32,64,6,512)
    float* a4  = out + XC_ELEMS;             // (32,1,512,512)

    k_conv   <<<dim3(TV/128, NB), 256>>>(x, conv_w, conv_b);
    k_x10    <<<dim3(VV/128, NB), 128>>>(l1_w, l2_w, l2_b);
    k_softmax<<<NB*VV, 256>>>(A, l1_b, a4);
    k_gemm   <<<dim3(512/128, 384/128, NB), 256>>>(a4, out);
}

// round 10
// speedup vs baseline: 2.6221x; 2.6221x over previous
#include <cuda_runtime.h>
#include <cuda_fp16.h>
#include <cstdint>

// Problem constants
#define NB   32
#define CIN  64
#define COUT 64
#define TT   6
#define VV   512
#define TV   (TT*VV)            // 3072
#define MROWS 384               // COUT*TT = GEMM M per batch
#define XC_ELEMS (NB*COUT*TV)   // 6,291,456
#define NEG_FILL  (-1000.0f)
#define SLOPE     (0.2f)

// Scratch (device globals; no allocation allowed)
__device__ float  g_xc[XC_ELEMS];            // fp32 xc (for k_x10)
__device__ __half g_xc_hi[XC_ELEMS];         // fp16 split of xc
__device__ __half g_xc_lo[XC_ELEMS];
__device__ __half g_a4t_hi[NB*VV*VV];        // fp16 split of a4^T
__device__ __half g_a4t_lo[NB*VV*VV];
__device__ float  g_si[NB*VV];
__device__ float  g_sj[NB*VV];

// ---------------------------------------------------------------------------
// Kernel 1: xc = conv_w @ x + b ; also emits fp16 hi/lo split of xc
// ---------------------------------------------------------------------------
__global__ __launch_bounds__(256) void k_conv(const float* __restrict__ x,
                                              const float* __restrict__ W,
                                              const float* __restrict__ b) {
    __shared__ float sW[COUT*CIN];
    __shared__ float sX[CIN][128];
    const int n  = blockIdx.y;
    const int p0 = blockIdx.x * 128;
    const int tid = threadIdx.x;

    for (int idx = tid; idx < COUT*CIN; idx += 256) sW[idx] = W[idx];
    const float* xb = x + (size_t)n * CIN * TV;
    for (int idx = tid; idx < CIN*128; idx += 256) {
        int i = idx >> 7, c = idx & 127;
        sX[i][c] = xb[i*TV + p0 + c];
    }
    __syncthreads();

    const int tx = tid & 31;
    const int ty = tid >> 5;
    float acc[8][4];
    #pragma unroll
    for (int a = 0; a < 8; a++)
        #pragma unroll
        for (int q = 0; q < 4; q++) acc[a][q] = 0.f;

    #pragma unroll 8
    for (int i = 0; i < CIN; i++) {
        float4 xv = *(const float4*)&sX[i][tx*4];
        #pragma unroll
        for (int a = 0; a < 8; a++) {
            float w = sW[(ty*8 + a)*CIN + i];
            acc[a][0] += w * xv.x;
            acc[a][1] += w * xv.y;
            acc[a][2] += w * xv.z;
            acc[a][3] += w * xv.w;
        }
    }

    float*  xcb = g_xc    + (size_t)n * COUT * TV;
    __half* hib = g_xc_hi + (size_t)n * COUT * TV;
    __half* lob = g_xc_lo + (size_t)n * COUT * TV;
    #pragma unroll
    for (int a = 0; a < 8; a++) {
        int o = ty*8 + a;
        float bias = b[o];
        float v0 = acc[a][0]+bias, v1 = acc[a][1]+bias;
        float v2 = acc[a][2]+bias, v3 = acc[a][3]+bias;
        size_t off = (size_t)o*TV + p0 + tx*4;
        *(float4*)&xcb[off] = make_float4(v0, v1, v2, v3);
        __half h0 = __float2half_rn(v0), h1 = __float2half_rn(v1);
        __half h2 = __float2half_rn(v2), h3 = __float2half_rn(v3);
        __half l0 = __float2half_rn(v0 - __half2float(h0));
        __half l1 = __float2half_rn(v1 - __half2float(h1));
        __half l2 = __float2half_rn(v2 - __half2float(h2));
        __half l3 = __float2half_rn(v3 - __half2float(h3));
        *(__half2*)&hib[off]   = __halves2half2(h0, h1);
        *(__half2*)&hib[off+2] = __halves2half2(h2, h3);
        *(__half2*)&lob[off]   = __halves2half2(l0, l1);
        *(__half2*)&lob[off+2] = __halves2half2(l2, l3);
    }
}

// ---------------------------------------------------------------------------
// Kernel 2: fused temporal contraction + attention projections (fp32)
// ---------------------------------------------------------------------------
__global__ __launch_bounds__(128) void k_x10(const float* __restrict__ l1w,
                                             const float* __restrict__ l2w,
                                             const float* __restrict__ l2b) {
    const int n = blockIdx.y;
    const int v = blockIdx.x * 128 + threadIdx.x;

    float w2[TT];
    #pragma unroll
    for (int t = 0; t < TT; t++) w2[t] = l2w[t];
    const float bias = l2b[0];

    const float* xcb = g_xc + (size_t)n * COUT * TV;
    float si = 0.f, sj = 0.f;
    for (int c = 0; c < COUT; c++) {
        float acc = bias;
        #pragma unroll
        for (int t = 0; t < TT; t++)
            acc += xcb[(c*TT + t)*VV + v] * w2[t];
        si += acc * l1w[c];
        sj += acc * l1w[COUT + c];
    }
    g_si[n*VV + v] = si;
    g_sj[n*VV + v] = sj;
}

// ---------------------------------------------------------------------------
// Kernel 3: scores -> leaky_relu -> mask -> softmax -> a4 (fp32 output)
// ---------------------------------------------------------------------------
__global__ __launch_bounds__(256) void k_softmax(const float* __restrict__ A,
                                                 const float* __restrict__ l1b,
                                                 float* __restrict__ a4) {
    const int row = blockIdx.x;
    const int n = row >> 9;
    const int i = row & 511;
    const int tid = threadIdx.x;
    const int lane = tid & 31, warp = tid >> 5;

    __shared__ float red[10];

    const float si = g_si[row];
    const float* sjp = g_sj + n*VV;
    const float* maskp = A + ((size_t)(n*8 + 7))*VV*VV + (size_t)i*VV;
    const float b = l1b[0];

    float v0, v1;
    {
        int j = tid;
        float s = si + sjp[j] + b;
        s = (s >= 0.f) ? s : SLOPE * s;
        if (maskp[j] == 0.f) s = NEG_FILL;
        v0 = s;
        j = tid + 256;
        s = si + sjp[j] + b;
        s = (s >= 0.f) ? s : SLOPE * s;
        if (maskp[j] == 0.f) s = NEG_FILL;
        v1 = s;
    }

    float m = fmaxf(v0, v1);
    #pragma unroll
    for (int off = 16; off; off >>= 1) m = fmaxf(m, __shfl_xor_sync(~0u, m, off));
    if (lane == 0) red[warp] = m;
    __syncthreads();
    if (tid == 0) {
        float mm = red[0];
        #pragma unroll
        for (int w = 1; w < 8; w++) mm = fmaxf(mm, red[w]);
        red[8] = mm;
    }
    __syncthreads();
    const float vmax = red[8];

    float e0 = __expf(v0 - vmax);
    float e1 = __expf(v1 - vmax);
    float s = e0 + e1;
    #pragma unroll
    for (int off = 16; off; off >>= 1) s += __shfl_xor_sync(~0u, s, off);
    if (lane == 0) red[warp] = s;
    __syncthreads();
    if (tid == 0) {
        float ss = red[0];
        #pragma unroll
        for (int w = 1; w < 8; w++) ss += red[w];
        red[9] = ss;
    }
    __syncthreads();
    const float inv = 1.0f / red[9];

    float* outp = a4 + (size_t)row * VV;
    outp[tid]       = e0 * inv;
    outp[tid + 256] = e1 * inv;
}

// ---------------------------------------------------------------------------
// Kernel 4: transpose a4 -> a4T with fp16 hi/lo split.  32x32 tiles.
// ---------------------------------------------------------------------------
__global__ __launch_bounds__(256) void k_tr(const float* __restrict__ a4) {
    __shared__ float tile[32][33];
    const int n  = blockIdx.z;
    const int i0 = blockIdx.x * 32;
    const int j0 = blockIdx.y * 32;
    const int tx = threadIdx.x & 31;
    const int ty = threadIdx.x >> 5;   // 0..7

    const float* src = a4 + ((size_t)n*VV + i0)*VV + j0;
    #pragma unroll
    for (int r = 0; r < 4; r++)
        tile[ty*4 + r][tx] = src[(size_t)(ty*4 + r)*VV + tx];
    __syncthreads();

    size_t dstb = ((size_t)n*VV + j0)*VV + i0;
    #pragma unroll
    for (int r = 0; r < 4; r++) {
        float v = tile[tx][ty*4 + r];      // a4[i0+tx][j0+ty*4+r]
        __half h = __float2half_rn(v);
        __half l = __float2half_rn(v - __half2float(h));
        size_t d = dstb + (size_t)(ty*4 + r)*VV + tx;
        g_a4t_hi[d] = h;
        g_a4t_lo[d] = l;
    }
}

// ---------------------------------------------------------------------------
// Kernel 5: HMMA GEMM  out[n](384x512) = xc @ a4, 3-pass fp16 hi/lo split.
// CTA 128x128, 8 warps (2x4) of 64x32. K chunks of 64, 2-stage cp.async.
// smem: 2 stages x (A 16KB + B 16KB) = 64KB dynamic, SW128 swizzle + ldmatrix
// ---------------------------------------------------------------------------
#define KC 64
#define STAGE 32768u
#define SMEM_DYN (2*32768)

__device__ __forceinline__ uint32_t swz(uint32_t off) { return off ^ ((off >> 3) & 0x70); }

__device__ __forceinline__ void issue_chunk(int t, int tid, int m0, int n0,
                                            const __half* ahi, const __half* alo,
                                            const __half* bhi, const __half* blo,
                                            uint32_t sbase) {
    if (t >= 24) { asm volatile("cp.async.commit_group;" ::: "memory"); return; }
    const int p  = t >> 3;              // pass 0..2
    const int cc = (t & 7) * KC;        // k offset
    const __half* Ap = (p == 2) ? alo : ahi;   // passes: hi*hi, hi*lo, lo*hi
    const __half* Bp = (p == 1) ? blo : bhi;
    const uint32_t st = sbase + (uint32_t)(t & 1) * STAGE;
    #pragma unroll
    for (int r = 0; r < 8; r++) {
        int idx = tid + r*256;          // 0..2047
        int isB = idx >> 10;
        int row = (idx >> 3) & 127;
        int g   = idx & 7;
        const __half* src = (isB ? Bp + (size_t)(n0 + row)*VV
                                 : Ap + (size_t)(m0 + row)*VV) + cc + g*8;
        uint32_t dst = st + (uint32_t)isB*16384u + swz((uint32_t)(row*128 + g*16));
        asm volatile("cp.async.cg.shared.global [%0], [%1], 16;" :: "r"(dst), "l"(src));
    }
    asm volatile("cp.async.commit_group;" ::: "memory");
}

__global__ __launch_bounds__(256) void k_mma(float* __restrict__ out) {
    extern __shared__ char smem[];
    const uint32_t sbase = (uint32_t)__cvta_generic_to_shared(smem);
    const int tid = threadIdx.x;
    const int lane = tid & 31, wid = tid >> 5;
    const int wm = wid >> 2, wn = wid & 3;          // warp grid 2(M) x 4(N)
    const int nb = blockIdx.z;
    const int m0 = blockIdx.y * 128, n0 = blockIdx.x * 128;

    const __half* ahi = g_xc_hi  + (size_t)nb * MROWS * VV;
    const __half* alo = g_xc_lo  + (size_t)nb * MROWS * VV;
    const __half* bhi = g_a4t_hi + (size_t)nb * VV * VV;
    const __half* blo = g_a4t_lo + (size_t)nb * VV * VV;

    float c[4][4][4];
    #pragma unroll
    for (int mi = 0; mi < 4; mi++)
        #pragma unroll
        for (int ni = 0; ni < 4; ni++)
            #pragma unroll
            for (int q = 0; q < 4; q++) c[mi][ni][q] = 0.f;

    const int lrow = lane & 15;         // ldmatrix row within 16
    const int lkg  = lane >> 4;         // 0/1 -> +8 halves

    issue_chunk(0, tid, m0, n0, ahi, alo, bhi, blo, sbase);

    for (int t = 0; t < 24; t++) {
        issue_chunk(t + 1, tid, m0, n0, ahi, alo, bhi, blo, sbase);
        if (t < 23) asm volatile("cp.async.wait_group 1;" ::: "memory");
        else        asm volatile("cp.async.wait_group 0;" ::: "memory");
        __syncthreads();

        const uint32_t st = sbase + (uint32_t)(t & 1) * STAGE;
        #pragma unroll
        for (int kk = 0; kk < 4; kk++) {
            const int khalf = kk*16 + lkg*8;
            uint32_t a[4][4];
            #pragma unroll
            for (int mi = 0; mi < 4; mi++) {
                int row = wm*64 + mi*16 + lrow;
                uint32_t addr = st + swz((uint32_t)(row*128 + khalf*2));
                asm volatile("ldmatrix.sync.aligned.m8n8.x4.shared.b16 {%0,%1,%2,%3}, [%4];"
                    : "=r"(a[mi][0]), "=r"(a[mi][1]), "=r"(a[mi][2]), "=r"(a[mi][3])
                    : "r"(addr));
            }
            uint32_t bf[2][4];
            #pragma unroll
            for (int nh = 0; nh < 2; nh++) {
                int row = wn*32 + nh*16 + lrow;
                uint32_t addr = st + 16384u + swz((uint32_t)(row*128 + khalf*2));
                asm volatile("ldmatrix.sync.aligned.m8n8.x4.shared.b16 {%0,%1,%2,%3}, [%4];"
                    : "=r"(bf[nh][0]), "=r"(bf[nh][1]), "=r"(bf[nh][2]), "=r"(bf[nh][3])
                    : "r"(addr));
            }
            #pragma unroll
            for (int mi = 0; mi < 4; mi++)
                #pragma unroll
                for (int ni = 0; ni < 4; ni++) {
                    uint32_t b0 = bf[ni>>1][ni & 1];
                    uint32_t b1 = bf[ni>>1][2 + (ni & 1)];
                    asm volatile(
                        "mma.sync.aligned.m16n8k16.row.col.f32.f16.f16.f32 "
                        "{%0,%1,%2,%3}, {%4,%5,%6,%7}, {%8,%9}, {%0,%1,%2,%3};"
                        : "+f"(c[mi][ni][0]), "+f"(c[mi][ni][1]),
                          "+f"(c[mi][ni][2]), "+f"(c[mi][ni][3])
                        : "r"(a[mi][0]), "r"(a[mi][1]), "r"(a[mi][2]), "r"(a[mi][3]),
                          "r"(b0), "r"(b1));
                }
        }
        __syncthreads();
    }

    // epilogue
    float* ob = out + (size_t)nb * MROWS * VV;
    const int r0    = m0 + wm*64 + (lane >> 2);
    const int cbase = n0 + wn*32 + (lane & 3)*2;
    #pragma unroll
    for (int mi = 0; mi < 4; mi++)
        #pragma unroll
        for (int ni = 0; ni < 4; ni++) {
            int r = r0 + mi*16, cl = cbase + ni*8;
            *(float2*)&ob[(size_t)r*VV + cl]     = make_float2(c[mi][ni][0], c[mi][ni][1]);
            *(float2*)&ob[(size_t)(r+8)*VV + cl] = make_float2(c[mi][ni][2], c[mi][ni][3]);
        }
}

// ---------------------------------------------------------------------------
extern "C" void kernel_launch(void* const* d_in, const int* in_sizes, int n_in,
                              void* d_out, int out_size) {
    const float* x      = (const float*)d_in[0];
    const float* A      = (const float*)d_in[1];
    const float* conv_w = (const float*)d_in[2];
    const float* conv_b = (const float*)d_in[3];
    const float* l1_w   = (const float*)d_in[4];
    const float* l1_b   = (const float*)d_in[5];
    const float* l2_w   = (const float*)d_in[6];
    const float* l2_b   = (const float*)d_in[7];

    float* out = (float*)d_out;              // (32,64,6,512)
    float* a4  = out + XC_ELEMS;             // (32,1,512,512)

    cudaFuncSetAttribute(k_mma, cudaFuncAttributeMaxDynamicSharedMemorySize, SMEM_DYN);

    k_conv   <<<dim3(TV/128, NB), 256>>>(x, conv_w, conv_b);
    k_x10    <<<dim3(VV/128, NB), 128>>>(l1_w, l2_w, l2_b);
    k_softmax<<<NB*VV, 256>>>(A, l1_b, a4);
    k_tr     <<<dim3(VV/32, VV/32, NB), 256>>>(a4);
    k_mma    <<<dim3(VV/128, MROWS/128, NB), 256, SMEM_DYN>>>(out);
}